// round 16
// baseline (speedup 1.0000x reference)
#include <cuda_runtime.h>
#include <cuda_bf16.h>
#include <math.h>
#include <stdint.h>

// ---------------------------------------------------------------------------
// Problem constants
// ---------------------------------------------------------------------------
constexpr int cB = 2, cS = 4096, cH = 768, cE = 2, cR = 4, cD = 256;
constexpr int cNC = 64, cL = 64;            // scan chunks: 64 chunks x 64 steps
constexpr int cER  = cE * cR;               // 8
constexpr int cBER = cB * cER;              // 16
constexpr int cBS  = cB * cS;               // 8192
constexpr int cKA  = 3072;                  // gate A width (and A buffer stride)
constexpr float cIMP = 0.05f;
constexpr float cEPS = 1e-6f;

// ---------------------------------------------------------------------------
// Device scratch (static: no allocations allowed)
// ---------------------------------------------------------------------------
__device__ float g_sr[cBS * cD];
__device__ float g_si[cBS * cD];
__device__ float g_cer[cBER * cNC * cD];
__device__ float g_cei[cBER * cNC * cD];
__device__ float g_cir[cBER * cNC * cD];
__device__ float g_cii[cBER * cNC * cD];
__device__ float g_S[cBS * cER * 7];        // per (b,s,e,r): 7 d-sums
__device__ float g_Mr[2 * 14 * cH];         // fused Wsh@Wfus complex matrix
__device__ float g_Mi[2 * 14 * cH];
__device__ float g_MpR[8 * 28 * cH];        // mc partials (8 k-segments)
__device__ float g_MpI[8 * 28 * cH];
__device__ float g_bcr[cH];
__device__ float g_bci[cH];
__device__ float g_fur[cBS * cH];           // fp32 fur for final epilogue

// tf32 GEMM operands
__device__ __align__(16) float g_Atf[(size_t)cBS * cKA];   // [x|fur|fui|z] tf32
__device__ __align__(16) float g_Btf[cH * cKA];            // Wgate^T [768][3072]
__device__ __align__(16) float g_Bsig_tf[512 * cH];        // [Wsig_r|Wsig_i]^T [512][768]

// ---------------------------------------------------------------------------
// PTX helpers (sm_80-class only: mma.sync / cp.async / cvt.tf32)
// ---------------------------------------------------------------------------
__device__ __forceinline__ uint32_t smem_u32(const void* p) {
    uint32_t a;
    asm("{ .reg .u64 t; cvta.to.shared.u64 t, %1; cvt.u32.u64 %0, t; }" : "=r"(a) : "l"(p));
    return a;
}

__device__ __forceinline__ void cp_async16(uint32_t dst, const void* src) {
    asm volatile("cp.async.cg.shared.global [%0], [%1], 16;" :: "r"(dst), "l"(src));
}
__device__ __forceinline__ void cp_commit() {
    asm volatile("cp.async.commit_group;" ::: "memory");
}
template <int N>
__device__ __forceinline__ void cp_wait() {
    asm volatile("cp.async.wait_group %0;" :: "n"(N) : "memory");
}

// tf32 m16n8k8 mma: A 4 regs, B 2 regs, C 4 regs fp32
__device__ __forceinline__ void mma_tf32(float* c, const uint32_t* a,
                                         uint32_t b0, uint32_t b1) {
    asm volatile(
        "mma.sync.aligned.m16n8k8.row.col.f32.tf32.tf32.f32 "
        "{%0,%1,%2,%3}, {%4,%5,%6,%7}, {%8,%9}, {%0,%1,%2,%3};"
        : "+f"(c[0]), "+f"(c[1]), "+f"(c[2]), "+f"(c[3])
        : "r"(a[0]), "r"(a[1]), "r"(a[2]), "r"(a[3]), "r"(b0), "r"(b1));
}

__device__ __forceinline__ float tf32_round(float v) {
    uint32_t r;
    asm("cvt.rna.tf32.f32 %0, %1;" : "=r"(r) : "f"(v));
    return __uint_as_float(r);
}

// ---------------------------------------------------------------------------
// misc helpers
// ---------------------------------------------------------------------------
__device__ __forceinline__ void lambda_of(const float* __restrict__ ld_,
                                          const float* __restrict__ th_,
                                          int erd, float& lr, float& li) {
    float ld  = ld_[erd];
    float sp  = (ld > 0.f) ? (ld + log1pf(expf(-ld))) : log1pf(expf(ld));
    float mag = expf(-sp);
    float th  = th_[erd];
    lr = mag * cosf(th);
    li = mag * sinf(th);
}
__device__ __forceinline__ float sigmoidf_(float v) { return 1.0f / (1.0f + expf(-v)); }

// ---------------------------------------------------------------------------
// Prep kernel: x -> tf32-rounded fp32 into A cols [0,768)
// ---------------------------------------------------------------------------
__global__ void convert_x(const float* __restrict__ x) {
    const int i = blockIdx.x * 256 + threadIdx.x;      // per float4
    const float4 v = ((const float4*)x)[i];
    const int e   = i * 4;
    const int row = e / cH, col = e % cH;
    const size_t o = (size_t)row * cKA + col;
    float4 q;
    q.x = tf32_round(v.x); q.y = tf32_round(v.y);
    q.z = tf32_round(v.z); q.w = tf32_round(v.w);
    *(float4*)(g_Atf + o) = q;
}

// ---------------------------------------------------------------------------
// Generic prep: W (K x N row-major) -> dst[(drowoff + n)][k] tf32-rounded.
// grid (K/32, N/32), block (32, 8)
// ---------------------------------------------------------------------------
__global__ void transpose_tf32(const float* __restrict__ W, int N,
                               float* __restrict__ dst, size_t dstride,
                               int drowoff) {
    __shared__ float tile[32][33];
    const int k0 = blockIdx.x * 32, n0 = blockIdx.y * 32;
    const int tx = threadIdx.x, ty = threadIdx.y;
    for (int j = ty; j < 32; j += 8)
        tile[j][tx] = W[(size_t)(k0 + j) * N + n0 + tx];
    __syncthreads();
    for (int j = ty; j < 32; j += 8)
        dst[(size_t)(drowoff + n0 + j) * dstride + (k0 + tx)] = tf32_round(tile[tx][j]);
}

// ---------------------------------------------------------------------------
// tf32 single-pass GEMM (templated, R14-measured 2-stage schedule):
// C(8192 x N) = A(8192 x KTOT) @ B^T.
// A = g_Atf (stride cKA, cols [0,KTOT)). B = Btf [N][KTOT] K-major tf32.
// 128x128x32 CTA tile, 8 warps (2x4), warp tile 64x32, mma.m16n8k8.
// 2-stage cp.async, full-drain wait<0>, compile-time (t&1) buffer indexing
// (3-stage + runtime ring index caused register spills under the 128-reg cap
//  -> 10x regression in R15; do not reintroduce).
// MODE 0 (sig): out split to g_sr/g_si with bias p0/p1.
// MODE 1 (gate): out = p0(x) + g_fur * sigmoid(acc + p1(bgate)).
// ---------------------------------------------------------------------------
constexpr int S4 = 36;                         // smem row stride in words (144B)
constexpr int TSTAGE = 128 * S4;               // words per matrix per stage
constexpr int GEMM_SMEM_BYTES = 2 * TSTAGE * 2 * 4;   // 2 stages x (A+B) x fp32

template <int KTOT, int MODE>
__global__ __launch_bounds__(256, 2) void gemm_tf32(
    const float* __restrict__ Btf,
    const float* __restrict__ p0, const float* __restrict__ p1,
    float* __restrict__ out) {
    extern __shared__ __align__(16) float smem[];
    float* sA = smem;                  // [2][128*S4]
    float* sB = smem + 2 * TSTAGE;     // [2][128*S4]

    const int tid = threadIdx.x;
    const int wid = tid >> 5, lane = tid & 31;
    const int wm = wid >> 2, wn = wid & 3;          // 2 x 4 warp grid
    const int bn = blockIdx.x, bm = blockIdx.y;
    const int rowBase = bm * 128, colBase = bn * 128;

    const uint32_t sA0 = smem_u32(sA);
    const uint32_t sB0 = smem_u32(sB);

    constexpr int NT = KTOT / 32;

    // global->smem: 2 threads per row, 16 floats (64B) each
    const int lrow = tid >> 1;
    const int lhw  = (tid & 1) * 16;

    auto load_tile = [&](int t, int buf) {
        const int k0 = t * 32;
        const float* ga = g_Atf + (size_t)(rowBase + lrow) * cKA + k0 + lhw;
        const float* gb = Btf + (size_t)(colBase + lrow) * KTOT + k0 + lhw;
        const uint32_t da = sA0 + (buf * TSTAGE + lrow * S4 + lhw) * 4;
        const uint32_t db = sB0 + (buf * TSTAGE + lrow * S4 + lhw) * 4;
#pragma unroll
        for (int q = 0; q < 4; q++) {
            cp_async16(da + q * 16, ga + q * 4);
            cp_async16(db + q * 16, gb + q * 4);
        }
    };

    float acc[4][4][4];
#pragma unroll
    for (int mi = 0; mi < 4; mi++)
#pragma unroll
        for (int ni = 0; ni < 4; ni++)
#pragma unroll
            for (int q = 0; q < 4; q++) acc[mi][ni][q] = 0.f;

    load_tile(0, 0);
    cp_commit();

    const int fq = lane >> 2;          // 0..7
    const int fk = lane & 3;           // 0..3

    for (int t = 0; t < NT; t++) {
        cp_wait<0>();
        __syncthreads();               // compute(t-1) retired; stage t landed
        if (t + 1 < NT) {
            load_tile(t + 1, (t + 1) & 1);
            cp_commit();
        }

        const float* aBuf = sA + (t & 1) * TSTAGE;
        const float* bBuf = sB + (t & 1) * TSTAGE;

#pragma unroll
        for (int kc = 0; kc < 4; kc++) {
            const int kb = kc * 8 + fk;
            uint32_t af[4][4];
#pragma unroll
            for (int mi = 0; mi < 4; mi++) {
                const float* p = aBuf + (wm * 64 + mi * 16 + fq) * S4 + kb;
                af[mi][0] = __float_as_uint(p[0]);
                af[mi][1] = __float_as_uint(p[8 * S4]);
                af[mi][2] = __float_as_uint(p[4]);
                af[mi][3] = __float_as_uint(p[8 * S4 + 4]);
            }
            uint32_t bf[4][2];
#pragma unroll
            for (int ni = 0; ni < 4; ni++) {
                const float* p = bBuf + (wn * 32 + ni * 8 + fq) * S4 + kb;
                bf[ni][0] = __float_as_uint(p[0]);
                bf[ni][1] = __float_as_uint(p[4]);
            }
#pragma unroll
            for (int mi = 0; mi < 4; mi++)
#pragma unroll
                for (int ni = 0; ni < 4; ni++)
                    mma_tf32(acc[mi][ni], af[mi], bf[ni][0], bf[ni][1]);
        }
    }

    // ---- epilogue (C fragment layout identical to m16n8k16) ----
#pragma unroll
    for (int mi = 0; mi < 4; mi++) {
#pragma unroll
        for (int ni = 0; ni < 4; ni++) {
            const int m0 = rowBase + wm * 64 + mi * 16 + (lane >> 2);
            const int n  = colBase + wn * 32 + ni * 8 + (lane & 3) * 2;
#pragma unroll
            for (int half = 0; half < 2; half++) {
                const int r = m0 + half * 8;
                const float c0 = acc[mi][ni][half * 2 + 0];
                const float c1 = acc[mi][ni][half * 2 + 1];
                if constexpr (MODE == 1) {
                    const float2 xv = *(const float2*)(p0 + (size_t)r * cH + n);
                    const float2 fv = *(const float2*)(g_fur + (size_t)r * cH + n);
                    const float2 bv = *(const float2*)(p1 + n);
                    float2 ov;
                    ov.x = xv.x + fv.x * sigmoidf_(c0 + bv.x);
                    ov.y = xv.y + fv.y * sigmoidf_(c1 + bv.y);
                    *(float2*)(out + (size_t)r * cH + n) = ov;
                } else {
                    float* dst; const float* bias; int col;
                    if (n < 256) { dst = g_sr; bias = p0; col = n; }
                    else         { dst = g_si; bias = p1; col = n - 256; }
                    const float2 bv = *(const float2*)(bias + col);
                    float2 ov;
                    ov.x = c0 + bv.x;
                    ov.y = c1 + bv.y;
                    *(float2*)(dst + (size_t)r * cD + col) = ov;
                }
            }
        }
    }
}

// ---------------------------------------------------------------------------
// Scan pass1 — per (b,e,r,chunk), local chunk-end state (zero init)
// ---------------------------------------------------------------------------
__global__ void scan_pass1(const float* __restrict__ ld_, const float* __restrict__ th_,
                           const float* __restrict__ Br_, const float* __restrict__ Bi_) {
    const int blk = blockIdx.x;
    const int c   = blk % cNC;
    const int er  = blk / cNC;
    const int b   = er / cER;
    const int erx = er % cER;
    const int d   = threadIdx.x;
    const int erd = erx * cD + d;

    float lr, li; lambda_of(ld_, th_, erd, lr, li);
    const float Br = Br_[erd], Bi = Bi_[erd];

    float hr = 0.f, hi = 0.f;
    const int t0 = c * cL;
    for (int t = t0; t < t0 + cL; t++) {
        float xr = g_sr[(b * cS + t) * cD + d];
        float xi = g_si[(b * cS + t) * cD + d];
        float ur = Br * xr - Bi * xi;
        float ui = Br * xi + Bi * xr;
        float nr = lr * hr - li * hi + ur;
        float ni = lr * hi + li * hr + ui;
        hr = nr; hi = ni;
    }
    const int idx = (er * cNC + c) * cD + d;
    g_cer[idx] = hr;
    g_cei[idx] = hi;
}

// ---------------------------------------------------------------------------
// Scan pass2 — serial combine across chunks per channel
// ---------------------------------------------------------------------------
__global__ void scan_pass2(const float* __restrict__ ld_, const float* __restrict__ th_) {
    const int gid = blockIdx.x * blockDim.x + threadIdx.x;
    const int d   = gid & (cD - 1);
    const int er  = gid >> 8;
    const int erx = er % cER;
    const int erd = erx * cD + d;

    float lr, li; lambda_of(ld_, th_, erd, lr, li);
    float ar = lr, ai = li;
#pragma unroll
    for (int q = 0; q < 6; q++) {
        float nr = ar * ar - ai * ai;
        float ni = 2.f * ar * ai;
        ar = nr; ai = ni;
    }
    float Sr = 0.f, Si = 0.f;
    for (int c = 0; c < cNC; c++) {
        const int idx = (er * cNC + c) * cD + d;
        g_cir[idx] = Sr;
        g_cii[idx] = Si;
        float nr = ar * Sr - ai * Si + g_cer[idx];
        float ni = ar * Si + ai * Sr + g_cei[idx];
        Sr = nr; Si = ni;
    }
}

// ---------------------------------------------------------------------------
// Scan pass3 — replay with carry, fused normalize + twist + 7 d-sums.
// Double-buffered smem reductions: ONE __syncthreads per timestep.
// ---------------------------------------------------------------------------
__global__ void scan_pass3(const float* __restrict__ ld_, const float* __restrict__ th_,
                           const float* __restrict__ Br_, const float* __restrict__ Bi_) {
    const int blk = blockIdx.x;
    const int c   = blk % cNC;
    const int er  = blk / cNC;
    const int b   = er / cER;
    const int erx = er % cER;
    const int d   = threadIdx.x;
    const int erd = erx * cD + d;
    const int lane = d & 31, warp = d >> 5;

    float lr, li; lambda_of(ld_, th_, erd, lr, li);
    const float Br = Br_[erd], Bi = Bi_[erd];

    const int cidx = (er * cNC + c) * cD + d;
    float hr = g_cir[cidx], hi = g_cii[cidx];

    __shared__ float sredp[2][8];
    __shared__ float sred7[2][8][7];

    const int t0 = c * cL;
    const int sbase = (b * cS) * (cER * 7) + erx * 7 + d;   // valid only d<7
    for (int t = t0; t < t0 + cL; t++) {
        float xr = g_sr[(b * cS + t) * cD + d];
        float xi = g_si[(b * cS + t) * cD + d];
        float ur = Br * xr - Bi * xi;
        float ui = Br * xi + Bi * xr;
        float nhr = lr * hr - li * hi + ur;
        float nhi = lr * hi + li * hr + ui;
        hr = nhr; hi = nhi;

        float v = hr * hr + hi * hi;
#pragma unroll
        for (int off = 16; off > 0; off >>= 1) v += __shfl_xor_sync(0xffffffffu, v, off);
        if (lane == 0) sredp[t & 1][warp] = v;
        __syncthreads();                        // publishes sredp[t&1] AND sred7[(t-1)&1]
        float tot = 0.f;
#pragma unroll
        for (int w = 0; w < 8; w++) tot += sredp[t & 1][w];
        const float inv = rsqrtf(tot * (1.0f / cD) + cEPS);

        const float nr = hr * inv, ni = hi * inv;
        const float thr_ = tanhf(nr), thi_ = tanhf(ni);
        const float gr_ = nr * (1.f + cIMP * thi_);
        const float gi_ = ni * (1.f + cIMP * thr_);

        float s[7];
        s[0] = gr_;          s[1] = gi_;
        s[2] = gr_ * gr_;    s[3] = gi_ * gi_;
        s[4] = gr_ * gi_;
        s[5] = tanhf(gr_);   s[6] = tanhf(gi_);
#pragma unroll
        for (int k = 0; k < 7; k++) {
            float u = s[k];
#pragma unroll
            for (int off = 16; off > 0; off >>= 1) u += __shfl_xor_sync(0xffffffffu, u, off);
            if (lane == 0) sred7[t & 1][warp][k] = u;
        }
        // readback for PREVIOUS timestep (its writes were published by this sync)
        if (t > t0 && d < 7) {
            const int tp = t - 1;
            float tk = 0.f;
#pragma unroll
            for (int w = 0; w < 8; w++) tk += sred7[tp & 1][w][d];
            g_S[sbase + tp * (cER * 7)] = tk;
        }
    }
    __syncthreads();
    if (d < 7) {
        const int tp = t0 + cL - 1;
        float tk = 0.f;
#pragma unroll
        for (int w = 0; w < 8; w++) tk += sred7[tp & 1][w][d];
        g_S[sbase + tp * (cER * 7)] = tk;
    }
}

// ---------------------------------------------------------------------------
// Mc = Wsh (complex) @ Wfus (complex) — 8-way k-split + reduce
// ---------------------------------------------------------------------------
__global__ void mc_part(const float* __restrict__ Wsh_r, const float* __restrict__ Wsh_i,
                        const float* __restrict__ Wfus_r, const float* __restrict__ Wfus_i) {
    const int j = blockIdx.x;      // e*14 + f
    const int seg = blockIdx.y;    // 0..7
    const int e = j / 14;
    const int tid = threadIdx.x;
    const float* wr = &Wsh_r[j * cH];
    const float* wi = &Wsh_i[j * cH];
    float accr[3] = {0.f, 0.f, 0.f}, acci[3] = {0.f, 0.f, 0.f};
    const int h0 = seg * 96;
    for (int h = h0; h < h0 + 96; h++) {
        const float ar = wr[h], ai = wi[h];
        const float* fr_row = &Wfus_r[(size_t)(e * cH + h) * cH];
        const float* fi_row = &Wfus_i[(size_t)(e * cH + h) * cH];
#pragma unroll
        for (int q = 0; q < 3; q++) {
            const int col = tid + q * 256;
            const float br = fr_row[col], bi = fi_row[col];
            accr[q] += ar * br - ai * bi;
            acci[q] += ar * bi + ai * br;
        }
    }
#pragma unroll
    for (int q = 0; q < 3; q++) {
        g_MpR[(seg * 28 + j) * cH + tid + q * 256] = accr[q];
        g_MpI[(seg * 28 + j) * cH + tid + q * 256] = acci[q];
    }
}

__global__ void mc_reduce() {
    const int idx = blockIdx.x * 256 + threadIdx.x;   // 28*768 = 21504
    const int j = idx / cH, col = idx % cH;
    float ar = 0.f, ai = 0.f;
#pragma unroll
    for (int seg = 0; seg < 8; seg++) {
        ar += g_MpR[(seg * 28 + j) * cH + col];
        ai += g_MpI[(seg * 28 + j) * cH + col];
    }
    g_Mr[j * cH + col] = ar;
    g_Mi[j * cH + col] = ai;
}

// ---------------------------------------------------------------------------
// bc = bfus + bsh(complex) @ Wfus(complex)
// ---------------------------------------------------------------------------
__global__ void bc_kernel(const float* __restrict__ bsh_r, const float* __restrict__ bsh_i,
                          const float* __restrict__ Wfus_r, const float* __restrict__ Wfus_i,
                          const float* __restrict__ bfus_r, const float* __restrict__ bfus_i) {
    const int c = blockIdx.x * blockDim.x + threadIdx.x;
    if (c >= cH) return;
    float ar = bfus_r[c], ai = bfus_i[c];
    for (int k = 0; k < cE * cH; k++) {
        const float br = bsh_r[k], bi = bsh_i[k];
        const float wr = Wfus_r[(size_t)k * cH + c], wi = Wfus_i[(size_t)k * cH + c];
        ar += br * wr - bi * wi;
        ai += br * wi + bi * wr;
    }
    g_bcr[c] = ar;
    g_bci[c] = ai;
}

// ---------------------------------------------------------------------------
// fuse — features from g_S, complex GEMM (K=28) with Mc; writes fur (fp32)
// and tf32-rounded fur/fui/z into A cols [768, 3072).
// ---------------------------------------------------------------------------
__global__ void fuse_kernel() {
    const int bs0 = blockIdx.x * 8;
    const int tid = threadIdx.x;

    __shared__ float Sh[8][56];
    __shared__ float frs[8][28], fis[8][28];

    for (int i = tid; i < 8 * 56; i += 256) {
        const int row = i / 56, q = i % 56;
        Sh[row][q] = g_S[(bs0 + row) * 56 + q];
    }
    __syncthreads();

    if (tid < 8 * 28) {
        const int row = tid / 28, j = tid % 28;
        const int e = j / 14, idx = j % 14;
        const float* Se = &Sh[row][e * 28];
        const float invD  = 1.0f / cD;
        const float invRD = 1.0f / (cR * cD);
        float fr = 0.f, fi = 0.f;
        if (idx < 4) {
            fr = Se[idx * 7 + 0] * invD;
            fi = Se[idx * 7 + 1] * invD;
        } else if (idx < 8) {
            const int r = idx - 4;
            fr = (Se[r * 7 + 2] - Se[r * 7 + 3]) * invD;
            fi = 2.f * Se[r * 7 + 4] * invD;
        } else {
            float T[7];
#pragma unroll
            for (int k = 0; k < 7; k++)
                T[k] = Se[k] + Se[7 + k] + Se[14 + k] + Se[21 + k];
            switch (idx) {
                case 8:  fr = T[0] * invRD;              fi = T[1] * invRD;              break;
                case 9:  fr = (T[2] - T[3]) * invRD;     fi = 2.f * T[4] * invRD;        break;
                case 10: fr = (T[2] + T[3]) * invRD;     fi = 0.f;                       break;
                case 11: fr = T[5] * invRD;              fi = T[6] * invRD;              break;
                case 12: fr = sqrtf(T[2] * invRD + cEPS); fi = sqrtf(T[3] * invRD + cEPS); break;
                default: fr = T[4] * invRD;              fi = 0.f;                       break;
            }
        }
        frs[row][j] = fr;
        fis[row][j] = fi;
    }
    __syncthreads();

    float ar[8][3], ai[8][3];
#pragma unroll
    for (int r = 0; r < 8; r++)
#pragma unroll
        for (int q = 0; q < 3; q++) { ar[r][q] = 0.f; ai[r][q] = 0.f; }

    for (int j = 0; j < 28; j++) {
        float mr[3], mi[3];
#pragma unroll
        for (int q = 0; q < 3; q++) {
            const int c = tid + q * 256;
            mr[q] = g_Mr[j * cH + c];
            mi[q] = g_Mi[j * cH + c];
        }
#pragma unroll
        for (int row = 0; row < 8; row++) {
            const float fr = frs[row][j], fi = fis[row][j];
#pragma unroll
            for (int q = 0; q < 3; q++) {
                ar[row][q] += fr * mr[q] - fi * mi[q];
                ai[row][q] += fr * mi[q] + fi * mr[q];
            }
        }
    }

#pragma unroll
    for (int q = 0; q < 3; q++) {
        const int c = tid + q * 256;
        const float bcr = g_bcr[c], bci = g_bci[c];
#pragma unroll
        for (int row = 0; row < 8; row++) {
            const float fur = ar[row][q] + bcr;
            const float fui = ai[row][q] + bci;
            const float z   = fur * (fui * sigmoidf_(fui));
            const size_t o  = (size_t)(bs0 + row) * cH + c;
            g_fur[o] = fur;
            const size_t ao = (size_t)(bs0 + row) * cKA;
            g_Atf[ao + 768 + c]  = tf32_round(fur);
            g_Atf[ao + 1536 + c] = tf32_round(fui);
            g_Atf[ao + 2304 + c] = tf32_round(z);
        }
    }
}

// ---------------------------------------------------------------------------
// launch
// ---------------------------------------------------------------------------
extern "C" void kernel_launch(void* const* d_in, const int* in_sizes, int n_in,
                              void* d_out, int out_size) {
    (void)in_sizes; (void)n_in; (void)out_size;
    const float* x       = (const float*)d_in[0];
    const float* Wsig_r  = (const float*)d_in[1];
    const float* Wsig_i  = (const float*)d_in[2];
    const float* bsig_r  = (const float*)d_in[3];
    const float* bsig_i  = (const float*)d_in[4];
    const float* log_dec = (const float*)d_in[5];
    const float* theta   = (const float*)d_in[6];
    const float* Bin_r   = (const float*)d_in[7];
    const float* Bin_i   = (const float*)d_in[8];
    const float* Wsh_r   = (const float*)d_in[9];
    const float* Wsh_i   = (const float*)d_in[10];
    const float* bsh_r   = (const float*)d_in[11];
    const float* bsh_i   = (const float*)d_in[12];
    const float* Wfus_r  = (const float*)d_in[13];
    const float* Wfus_i  = (const float*)d_in[14];
    const float* bfus_r  = (const float*)d_in[15];
    const float* bfus_i  = (const float*)d_in[16];
    const float* Wgate   = (const float*)d_in[17];
    const float* bgate   = (const float*)d_in[18];
    float* out = (float*)d_out;

    // dynamic smem for the 2-stage tf32 GEMMs (host attr, no allocation)
    cudaFuncSetAttribute(gemm_tf32<cKA, 1>,
                         cudaFuncAttributeMaxDynamicSharedMemorySize, GEMM_SMEM_BYTES);
    cudaFuncSetAttribute(gemm_tf32<768, 0>,
                         cudaFuncAttributeMaxDynamicSharedMemorySize, GEMM_SMEM_BYTES);

    convert_x<<<cBS * cH / 4 / 256, 256>>>(x);
    transpose_tf32<<<dim3(cKA / 32, cH / 32), dim3(32, 8)>>>(Wgate, cH, g_Btf, cKA, 0);
    transpose_tf32<<<dim3(cH / 32, 256 / 32), dim3(32, 8)>>>(Wsig_r, 256, g_Bsig_tf, cH, 0);
    transpose_tf32<<<dim3(cH / 32, 256 / 32), dim3(32, 8)>>>(Wsig_i, 256, g_Bsig_tf, cH, 256);

    // sig: g_sr|g_si = x @ [Wsig_r|Wsig_i] + b   (tf32, N=512, K=768)
    gemm_tf32<768, 0><<<dim3(4, 64), 256, GEMM_SMEM_BYTES>>>(
        g_Bsig_tf, bsig_r, bsig_i, nullptr);

    scan_pass1<<<cBER * cNC, 256>>>(log_dec, theta, Bin_r, Bin_i);
    scan_pass2<<<cBER, 256>>>(log_dec, theta);
    scan_pass3<<<cBER * cNC, 256>>>(log_dec, theta, Bin_r, Bin_i);

    mc_part<<<dim3(28, 8), 256>>>(Wsh_r, Wsh_i, Wfus_r, Wfus_i);
    mc_reduce<<<28 * cH / 256, 256>>>();
    bc_kernel<<<3, 256>>>(bsh_r, bsh_i, Wfus_r, Wfus_i, bfus_r, bfus_i);
    fuse_kernel<<<cBS / 8, 256>>>();

    // gate: out = x + sigmoid([x|fur|fui|z] @ Wgate + bgate) * fur  (tf32)
    gemm_tf32<cKA, 1><<<dim3(6, 64), 256, GEMM_SMEM_BYTES>>>(
        g_Btf, x, bgate, out);
}

// round 17
// speedup vs baseline: 11.8715x; 11.8715x over previous
#include <cuda_runtime.h>
#include <cuda_bf16.h>
#include <math.h>
#include <stdint.h>

// ---------------------------------------------------------------------------
// Problem constants
// ---------------------------------------------------------------------------
constexpr int cB = 2, cS = 4096, cH = 768, cE = 2, cR = 4, cD = 256;
constexpr int cNC = 64, cL = 64;            // scan chunks: 64 chunks x 64 steps
constexpr int cER  = cE * cR;               // 8
constexpr int cBER = cB * cER;              // 16
constexpr int cBS  = cB * cS;               // 8192
constexpr int cKA  = 3072;                  // gate A width (and A buffer stride)
constexpr float cIMP = 0.05f;
constexpr float cEPS = 1e-6f;

// ---------------------------------------------------------------------------
// Device scratch (static: no allocations allowed).
// NOTE: these symbols must ONLY be referenced from device code. Passing them
// as kernel arguments from host code passes the HOST shadow address, which
// GB300's ATS happily services over NVLink-C2C at ~200 GB/s — the silent 10x
// regression of R15/R16.
// ---------------------------------------------------------------------------
__device__ float g_sr[cBS * cD];
__device__ float g_si[cBS * cD];
__device__ float g_cer[cBER * cNC * cD];
__device__ float g_cei[cBER * cNC * cD];
__device__ float g_cir[cBER * cNC * cD];
__device__ float g_cii[cBER * cNC * cD];
__device__ float g_S[cBS * cER * 7];        // per (b,s,e,r): 7 d-sums
__device__ float g_Mr[2 * 14 * cH];         // fused Wsh@Wfus complex matrix
__device__ float g_Mi[2 * 14 * cH];
__device__ float g_MpR[8 * 28 * cH];        // mc partials (8 k-segments)
__device__ float g_MpI[8 * 28 * cH];
__device__ float g_bcr[cH];
__device__ float g_bci[cH];
__device__ float g_fur[cBS * cH];           // fp32 fur for final epilogue

// tf32 GEMM operands
__device__ __align__(16) float g_Atf[(size_t)cBS * cKA];   // [x|fur|fui|z] tf32
__device__ __align__(16) float g_Btf[cH * cKA];            // Wgate^T [768][3072]
__device__ __align__(16) float g_Bsig_tf[512 * cH];        // [Wsig_r|Wsig_i]^T [512][768]

// ---------------------------------------------------------------------------
// PTX helpers (sm_80-class only: mma.sync / cp.async / cvt.tf32)
// ---------------------------------------------------------------------------
__device__ __forceinline__ uint32_t smem_u32(const void* p) {
    uint32_t a;
    asm("{ .reg .u64 t; cvta.to.shared.u64 t, %1; cvt.u32.u64 %0, t; }" : "=r"(a) : "l"(p));
    return a;
}

__device__ __forceinline__ void cp_async16(uint32_t dst, const void* src) {
    asm volatile("cp.async.cg.shared.global [%0], [%1], 16;" :: "r"(dst), "l"(src));
}
__device__ __forceinline__ void cp_commit() {
    asm volatile("cp.async.commit_group;" ::: "memory");
}
template <int N>
__device__ __forceinline__ void cp_wait() {
    asm volatile("cp.async.wait_group %0;" :: "n"(N) : "memory");
}

// tf32 m16n8k8 mma: A 4 regs, B 2 regs, C 4 regs fp32
__device__ __forceinline__ void mma_tf32(float* c, const uint32_t* a,
                                         uint32_t b0, uint32_t b1) {
    asm volatile(
        "mma.sync.aligned.m16n8k8.row.col.f32.tf32.tf32.f32 "
        "{%0,%1,%2,%3}, {%4,%5,%6,%7}, {%8,%9}, {%0,%1,%2,%3};"
        : "+f"(c[0]), "+f"(c[1]), "+f"(c[2]), "+f"(c[3])
        : "r"(a[0]), "r"(a[1]), "r"(a[2]), "r"(a[3]), "r"(b0), "r"(b1));
}

__device__ __forceinline__ float tf32_round(float v) {
    uint32_t r;
    asm("cvt.rna.tf32.f32 %0, %1;" : "=r"(r) : "f"(v));
    return __uint_as_float(r);
}

// ---------------------------------------------------------------------------
// misc helpers
// ---------------------------------------------------------------------------
__device__ __forceinline__ void lambda_of(const float* __restrict__ ld_,
                                          const float* __restrict__ th_,
                                          int erd, float& lr, float& li) {
    float ld  = ld_[erd];
    float sp  = (ld > 0.f) ? (ld + log1pf(expf(-ld))) : log1pf(expf(ld));
    float mag = expf(-sp);
    float th  = th_[erd];
    lr = mag * cosf(th);
    li = mag * sinf(th);
}
__device__ __forceinline__ float sigmoidf_(float v) { return 1.0f / (1.0f + expf(-v)); }

// ---------------------------------------------------------------------------
// Prep kernel: x -> tf32-rounded fp32 into A cols [0,768)
// ---------------------------------------------------------------------------
__global__ void convert_x(const float* __restrict__ x) {
    const int i = blockIdx.x * 256 + threadIdx.x;      // per float4
    const float4 v = ((const float4*)x)[i];
    const int e   = i * 4;
    const int row = e / cH, col = e % cH;
    const size_t o = (size_t)row * cKA + col;
    float4 q;
    q.x = tf32_round(v.x); q.y = tf32_round(v.y);
    q.z = tf32_round(v.z); q.w = tf32_round(v.w);
    *(float4*)(g_Atf + o) = q;
}

// ---------------------------------------------------------------------------
// Generic prep: W (K x N row-major) -> Bdst[(drowoff + n)][k] tf32-rounded.
// which = 0 -> g_Btf (stride cKA); which = 1 -> g_Bsig_tf (stride cH).
// Destination resolved in DEVICE code (host must not pass device globals).
// grid (K/32, N/32), block (32, 8)
// ---------------------------------------------------------------------------
__global__ void transpose_tf32(const float* __restrict__ W, int N,
                               int which, int drowoff) {
    __shared__ float tile[32][33];
    float* dst = (which == 0) ? g_Btf : g_Bsig_tf;
    const size_t dstride = (which == 0) ? (size_t)cKA : (size_t)cH;
    const int k0 = blockIdx.x * 32, n0 = blockIdx.y * 32;
    const int tx = threadIdx.x, ty = threadIdx.y;
    for (int j = ty; j < 32; j += 8)
        tile[j][tx] = W[(size_t)(k0 + j) * N + n0 + tx];
    __syncthreads();
    for (int j = ty; j < 32; j += 8)
        dst[(size_t)(drowoff + n0 + j) * dstride + (k0 + tx)] = tf32_round(tile[tx][j]);
}

// ---------------------------------------------------------------------------
// tf32 single-pass GEMM (templated, R14-measured 2-stage schedule):
// C(8192 x N) = A(8192 x KTOT) @ B^T.
// A = g_Atf (stride cKA, cols [0,KTOT)). B selected by MODE in device code:
//   MODE 0 -> g_Bsig_tf [512][768];  MODE 1 -> g_Btf [768][3072].
// 128x128x32 CTA tile, 8 warps (2x4), warp tile 64x32, mma.m16n8k8.
// 2-stage cp.async, full-drain wait<0>, compile-time (t&1) buffer indexing.
// MODE 0 (sig): out split to g_sr/g_si with bias p0/p1.
// MODE 1 (gate): out = p0(x) + g_fur * sigmoid(acc + p1(bgate)).
// ---------------------------------------------------------------------------
constexpr int S4 = 36;                         // smem row stride in words (144B)
constexpr int TSTAGE = 128 * S4;               // words per matrix per stage
constexpr int GEMM_SMEM_BYTES = 2 * TSTAGE * 2 * 4;   // 2 stages x (A+B) x fp32

template <int KTOT, int MODE>
__global__ __launch_bounds__(256, 2) void gemm_tf32(
    const float* __restrict__ p0, const float* __restrict__ p1,
    float* __restrict__ out) {
    extern __shared__ __align__(16) float smem[];
    float* sA = smem;                  // [2][128*S4]
    float* sB = smem + 2 * TSTAGE;     // [2][128*S4]

    const float* Btf = (MODE == 0) ? g_Bsig_tf : g_Btf;   // DEVICE-side symbol ref

    const int tid = threadIdx.x;
    const int wid = tid >> 5, lane = tid & 31;
    const int wm = wid >> 2, wn = wid & 3;          // 2 x 4 warp grid
    const int bn = blockIdx.x, bm = blockIdx.y;
    const int rowBase = bm * 128, colBase = bn * 128;

    const uint32_t sA0 = smem_u32(sA);
    const uint32_t sB0 = smem_u32(sB);

    constexpr int NT = KTOT / 32;

    // global->smem: 2 threads per row, 16 floats (64B) each
    const int lrow = tid >> 1;
    const int lhw  = (tid & 1) * 16;

    auto load_tile = [&](int t, int buf) {
        const int k0 = t * 32;
        const float* ga = g_Atf + (size_t)(rowBase + lrow) * cKA + k0 + lhw;
        const float* gb = Btf + (size_t)(colBase + lrow) * KTOT + k0 + lhw;
        const uint32_t da = sA0 + (buf * TSTAGE + lrow * S4 + lhw) * 4;
        const uint32_t db = sB0 + (buf * TSTAGE + lrow * S4 + lhw) * 4;
#pragma unroll
        for (int q = 0; q < 4; q++) {
            cp_async16(da + q * 16, ga + q * 4);
            cp_async16(db + q * 16, gb + q * 4);
        }
    };

    float acc[4][4][4];
#pragma unroll
    for (int mi = 0; mi < 4; mi++)
#pragma unroll
        for (int ni = 0; ni < 4; ni++)
#pragma unroll
            for (int q = 0; q < 4; q++) acc[mi][ni][q] = 0.f;

    load_tile(0, 0);
    cp_commit();

    const int fq = lane >> 2;          // 0..7
    const int fk = lane & 3;           // 0..3

    for (int t = 0; t < NT; t++) {
        cp_wait<0>();
        __syncthreads();               // compute(t-1) retired; stage t landed
        if (t + 1 < NT) {
            load_tile(t + 1, (t + 1) & 1);
            cp_commit();
        }

        const float* aBuf = sA + (t & 1) * TSTAGE;
        const float* bBuf = sB + (t & 1) * TSTAGE;

#pragma unroll
        for (int kc = 0; kc < 4; kc++) {
            const int kb = kc * 8 + fk;
            uint32_t af[4][4];
#pragma unroll
            for (int mi = 0; mi < 4; mi++) {
                const float* p = aBuf + (wm * 64 + mi * 16 + fq) * S4 + kb;
                af[mi][0] = __float_as_uint(p[0]);
                af[mi][1] = __float_as_uint(p[8 * S4]);
                af[mi][2] = __float_as_uint(p[4]);
                af[mi][3] = __float_as_uint(p[8 * S4 + 4]);
            }
            uint32_t bf[4][2];
#pragma unroll
            for (int ni = 0; ni < 4; ni++) {
                const float* p = bBuf + (wn * 32 + ni * 8 + fq) * S4 + kb;
                bf[ni][0] = __float_as_uint(p[0]);
                bf[ni][1] = __float_as_uint(p[4]);
            }
#pragma unroll
            for (int mi = 0; mi < 4; mi++)
#pragma unroll
                for (int ni = 0; ni < 4; ni++)
                    mma_tf32(acc[mi][ni], af[mi], bf[ni][0], bf[ni][1]);
        }
    }

    // ---- epilogue (C fragment layout identical to m16n8k16) ----
#pragma unroll
    for (int mi = 0; mi < 4; mi++) {
#pragma unroll
        for (int ni = 0; ni < 4; ni++) {
            const int m0 = rowBase + wm * 64 + mi * 16 + (lane >> 2);
            const int n  = colBase + wn * 32 + ni * 8 + (lane & 3) * 2;
#pragma unroll
            for (int half = 0; half < 2; half++) {
                const int r = m0 + half * 8;
                const float c0 = acc[mi][ni][half * 2 + 0];
                const float c1 = acc[mi][ni][half * 2 + 1];
                if constexpr (MODE == 1) {
                    const float2 xv = *(const float2*)(p0 + (size_t)r * cH + n);
                    const float2 fv = *(const float2*)(g_fur + (size_t)r * cH + n);
                    const float2 bv = *(const float2*)(p1 + n);
                    float2 ov;
                    ov.x = xv.x + fv.x * sigmoidf_(c0 + bv.x);
                    ov.y = xv.y + fv.y * sigmoidf_(c1 + bv.y);
                    *(float2*)(out + (size_t)r * cH + n) = ov;
                } else {
                    float* dst; const float* bias; int col;
                    if (n < 256) { dst = g_sr; bias = p0; col = n; }
                    else         { dst = g_si; bias = p1; col = n - 256; }
                    const float2 bv = *(const float2*)(bias + col);
                    float2 ov;
                    ov.x = c0 + bv.x;
                    ov.y = c1 + bv.y;
                    *(float2*)(dst + (size_t)r * cD + col) = ov;
                }
            }
        }
    }
}

// ---------------------------------------------------------------------------
// Scan pass1 — per (b,e,r,chunk), local chunk-end state (zero init)
// ---------------------------------------------------------------------------
__global__ void scan_pass1(const float* __restrict__ ld_, const float* __restrict__ th_,
                           const float* __restrict__ Br_, const float* __restrict__ Bi_) {
    const int blk = blockIdx.x;
    const int c   = blk % cNC;
    const int er  = blk / cNC;
    const int b   = er / cER;
    const int erx = er % cER;
    const int d   = threadIdx.x;
    const int erd = erx * cD + d;

    float lr, li; lambda_of(ld_, th_, erd, lr, li);
    const float Br = Br_[erd], Bi = Bi_[erd];

    float hr = 0.f, hi = 0.f;
    const int t0 = c * cL;
    for (int t = t0; t < t0 + cL; t++) {
        float xr = g_sr[(b * cS + t) * cD + d];
        float xi = g_si[(b * cS + t) * cD + d];
        float ur = Br * xr - Bi * xi;
        float ui = Br * xi + Bi * xr;
        float nr = lr * hr - li * hi + ur;
        float ni = lr * hi + li * hr + ui;
        hr = nr; hi = ni;
    }
    const int idx = (er * cNC + c) * cD + d;
    g_cer[idx] = hr;
    g_cei[idx] = hi;
}

// ---------------------------------------------------------------------------
// Scan pass2 — serial combine across chunks per channel
// ---------------------------------------------------------------------------
__global__ void scan_pass2(const float* __restrict__ ld_, const float* __restrict__ th_) {
    const int gid = blockIdx.x * blockDim.x + threadIdx.x;
    const int d   = gid & (cD - 1);
    const int er  = gid >> 8;
    const int erx = er % cER;
    const int erd = erx * cD + d;

    float lr, li; lambda_of(ld_, th_, erd, lr, li);
    float ar = lr, ai = li;
#pragma unroll
    for (int q = 0; q < 6; q++) {
        float nr = ar * ar - ai * ai;
        float ni = 2.f * ar * ai;
        ar = nr; ai = ni;
    }
    float Sr = 0.f, Si = 0.f;
    for (int c = 0; c < cNC; c++) {
        const int idx = (er * cNC + c) * cD + d;
        g_cir[idx] = Sr;
        g_cii[idx] = Si;
        float nr = ar * Sr - ai * Si + g_cer[idx];
        float ni = ar * Si + ai * Sr + g_cei[idx];
        Sr = nr; Si = ni;
    }
}

// ---------------------------------------------------------------------------
// Scan pass3 — replay with carry, fused normalize + twist + 7 d-sums.
// Double-buffered smem reductions: ONE __syncthreads per timestep.
// ---------------------------------------------------------------------------
__global__ void scan_pass3(const float* __restrict__ ld_, const float* __restrict__ th_,
                           const float* __restrict__ Br_, const float* __restrict__ Bi_) {
    const int blk = blockIdx.x;
    const int c   = blk % cNC;
    const int er  = blk / cNC;
    const int b   = er / cER;
    const int erx = er % cER;
    const int d   = threadIdx.x;
    const int erd = erx * cD + d;
    const int lane = d & 31, warp = d >> 5;

    float lr, li; lambda_of(ld_, th_, erd, lr, li);
    const float Br = Br_[erd], Bi = Bi_[erd];

    const int cidx = (er * cNC + c) * cD + d;
    float hr = g_cir[cidx], hi = g_cii[cidx];

    __shared__ float sredp[2][8];
    __shared__ float sred7[2][8][7];

    const int t0 = c * cL;
    const int sbase = (b * cS) * (cER * 7) + erx * 7 + d;   // valid only d<7
    for (int t = t0; t < t0 + cL; t++) {
        float xr = g_sr[(b * cS + t) * cD + d];
        float xi = g_si[(b * cS + t) * cD + d];
        float ur = Br * xr - Bi * xi;
        float ui = Br * xi + Bi * xr;
        float nhr = lr * hr - li * hi + ur;
        float nhi = lr * hi + li * hr + ui;
        hr = nhr; hi = nhi;

        float v = hr * hr + hi * hi;
#pragma unroll
        for (int off = 16; off > 0; off >>= 1) v += __shfl_xor_sync(0xffffffffu, v, off);
        if (lane == 0) sredp[t & 1][warp] = v;
        __syncthreads();                        // publishes sredp[t&1] AND sred7[(t-1)&1]
        float tot = 0.f;
#pragma unroll
        for (int w = 0; w < 8; w++) tot += sredp[t & 1][w];
        const float inv = rsqrtf(tot * (1.0f / cD) + cEPS);

        const float nr = hr * inv, ni = hi * inv;
        const float thr_ = tanhf(nr), thi_ = tanhf(ni);
        const float gr_ = nr * (1.f + cIMP * thi_);
        const float gi_ = ni * (1.f + cIMP * thr_);

        float s[7];
        s[0] = gr_;          s[1] = gi_;
        s[2] = gr_ * gr_;    s[3] = gi_ * gi_;
        s[4] = gr_ * gi_;
        s[5] = tanhf(gr_);   s[6] = tanhf(gi_);
#pragma unroll
        for (int k = 0; k < 7; k++) {
            float u = s[k];
#pragma unroll
            for (int off = 16; off > 0; off >>= 1) u += __shfl_xor_sync(0xffffffffu, u, off);
            if (lane == 0) sred7[t & 1][warp][k] = u;
        }
        // readback for PREVIOUS timestep (its writes were published by this sync)
        if (t > t0 && d < 7) {
            const int tp = t - 1;
            float tk = 0.f;
#pragma unroll
            for (int w = 0; w < 8; w++) tk += sred7[tp & 1][w][d];
            g_S[sbase + tp * (cER * 7)] = tk;
        }
    }
    __syncthreads();
    if (d < 7) {
        const int tp = t0 + cL - 1;
        float tk = 0.f;
#pragma unroll
        for (int w = 0; w < 8; w++) tk += sred7[tp & 1][w][d];
        g_S[sbase + tp * (cER * 7)] = tk;
    }
}

// ---------------------------------------------------------------------------
// Mc = Wsh (complex) @ Wfus (complex) — 8-way k-split + reduce
// ---------------------------------------------------------------------------
__global__ void mc_part(const float* __restrict__ Wsh_r, const float* __restrict__ Wsh_i,
                        const float* __restrict__ Wfus_r, const float* __restrict__ Wfus_i) {
    const int j = blockIdx.x;      // e*14 + f
    const int seg = blockIdx.y;    // 0..7
    const int e = j / 14;
    const int tid = threadIdx.x;
    const float* wr = &Wsh_r[j * cH];
    const float* wi = &Wsh_i[j * cH];
    float accr[3] = {0.f, 0.f, 0.f}, acci[3] = {0.f, 0.f, 0.f};
    const int h0 = seg * 96;
    for (int h = h0; h < h0 + 96; h++) {
        const float ar = wr[h], ai = wi[h];
        const float* fr_row = &Wfus_r[(size_t)(e * cH + h) * cH];
        const float* fi_row = &Wfus_i[(size_t)(e * cH + h) * cH];
#pragma unroll
        for (int q = 0; q < 3; q++) {
            const int col = tid + q * 256;
            const float br = fr_row[col], bi = fi_row[col];
            accr[q] += ar * br - ai * bi;
            acci[q] += ar * bi + ai * br;
        }
    }
#pragma unroll
    for (int q = 0; q < 3; q++) {
        g_MpR[(seg * 28 + j) * cH + tid + q * 256] = accr[q];
        g_MpI[(seg * 28 + j) * cH + tid + q * 256] = acci[q];
    }
}

__global__ void mc_reduce() {
    const int idx = blockIdx.x * 256 + threadIdx.x;   // 28*768 = 21504
    const int j = idx / cH, col = idx % cH;
    float ar = 0.f, ai = 0.f;
#pragma unroll
    for (int seg = 0; seg < 8; seg++) {
        ar += g_MpR[(seg * 28 + j) * cH + col];
        ai += g_MpI[(seg * 28 + j) * cH + col];
    }
    g_Mr[j * cH + col] = ar;
    g_Mi[j * cH + col] = ai;
}

// ---------------------------------------------------------------------------
// bc = bfus + bsh(complex) @ Wfus(complex)
// ---------------------------------------------------------------------------
__global__ void bc_kernel(const float* __restrict__ bsh_r, const float* __restrict__ bsh_i,
                          const float* __restrict__ Wfus_r, const float* __restrict__ Wfus_i,
                          const float* __restrict__ bfus_r, const float* __restrict__ bfus_i) {
    const int c = blockIdx.x * blockDim.x + threadIdx.x;
    if (c >= cH) return;
    float ar = bfus_r[c], ai = bfus_i[c];
    for (int k = 0; k < cE * cH; k++) {
        const float br = bsh_r[k], bi = bsh_i[k];
        const float wr = Wfus_r[(size_t)k * cH + c], wi = Wfus_i[(size_t)k * cH + c];
        ar += br * wr - bi * wi;
        ai += br * wi + bi * wr;
    }
    g_bcr[c] = ar;
    g_bci[c] = ai;
}

// ---------------------------------------------------------------------------
// fuse — features from g_S, complex GEMM (K=28) with Mc; writes fur (fp32)
// and tf32-rounded fur/fui/z into A cols [768, 3072).
// ---------------------------------------------------------------------------
__global__ void fuse_kernel() {
    const int bs0 = blockIdx.x * 8;
    const int tid = threadIdx.x;

    __shared__ float Sh[8][56];
    __shared__ float frs[8][28], fis[8][28];

    for (int i = tid; i < 8 * 56; i += 256) {
        const int row = i / 56, q = i % 56;
        Sh[row][q] = g_S[(bs0 + row) * 56 + q];
    }
    __syncthreads();

    if (tid < 8 * 28) {
        const int row = tid / 28, j = tid % 28;
        const int e = j / 14, idx = j % 14;
        const float* Se = &Sh[row][e * 28];
        const float invD  = 1.0f / cD;
        const float invRD = 1.0f / (cR * cD);
        float fr = 0.f, fi = 0.f;
        if (idx < 4) {
            fr = Se[idx * 7 + 0] * invD;
            fi = Se[idx * 7 + 1] * invD;
        } else if (idx < 8) {
            const int r = idx - 4;
            fr = (Se[r * 7 + 2] - Se[r * 7 + 3]) * invD;
            fi = 2.f * Se[r * 7 + 4] * invD;
        } else {
            float T[7];
#pragma unroll
            for (int k = 0; k < 7; k++)
                T[k] = Se[k] + Se[7 + k] + Se[14 + k] + Se[21 + k];
            switch (idx) {
                case 8:  fr = T[0] * invRD;              fi = T[1] * invRD;              break;
                case 9:  fr = (T[2] - T[3]) * invRD;     fi = 2.f * T[4] * invRD;        break;
                case 10: fr = (T[2] + T[3]) * invRD;     fi = 0.f;                       break;
                case 11: fr = T[5] * invRD;              fi = T[6] * invRD;              break;
                case 12: fr = sqrtf(T[2] * invRD + cEPS); fi = sqrtf(T[3] * invRD + cEPS); break;
                default: fr = T[4] * invRD;              fi = 0.f;                       break;
            }
        }
        frs[row][j] = fr;
        fis[row][j] = fi;
    }
    __syncthreads();

    float ar[8][3], ai[8][3];
#pragma unroll
    for (int r = 0; r < 8; r++)
#pragma unroll
        for (int q = 0; q < 3; q++) { ar[r][q] = 0.f; ai[r][q] = 0.f; }

    for (int j = 0; j < 28; j++) {
        float mr[3], mi[3];
#pragma unroll
        for (int q = 0; q < 3; q++) {
            const int c = tid + q * 256;
            mr[q] = g_Mr[j * cH + c];
            mi[q] = g_Mi[j * cH + c];
        }
#pragma unroll
        for (int row = 0; row < 8; row++) {
            const float fr = frs[row][j], fi = fis[row][j];
#pragma unroll
            for (int q = 0; q < 3; q++) {
                ar[row][q] += fr * mr[q] - fi * mi[q];
                ai[row][q] += fr * mi[q] + fi * mr[q];
            }
        }
    }

#pragma unroll
    for (int q = 0; q < 3; q++) {
        const int c = tid + q * 256;
        const float bcr = g_bcr[c], bci = g_bci[c];
#pragma unroll
        for (int row = 0; row < 8; row++) {
            const float fur = ar[row][q] + bcr;
            const float fui = ai[row][q] + bci;
            const float z   = fur * (fui * sigmoidf_(fui));
            const size_t o  = (size_t)(bs0 + row) * cH + c;
            g_fur[o] = fur;
            const size_t ao = (size_t)(bs0 + row) * cKA;
            g_Atf[ao + 768 + c]  = tf32_round(fur);
            g_Atf[ao + 1536 + c] = tf32_round(fui);
            g_Atf[ao + 2304 + c] = tf32_round(z);
        }
    }
}

// ---------------------------------------------------------------------------
// launch
// ---------------------------------------------------------------------------
extern "C" void kernel_launch(void* const* d_in, const int* in_sizes, int n_in,
                              void* d_out, int out_size) {
    (void)in_sizes; (void)n_in; (void)out_size;
    const float* x       = (const float*)d_in[0];
    const float* Wsig_r  = (const float*)d_in[1];
    const float* Wsig_i  = (const float*)d_in[2];
    const float* bsig_r  = (const float*)d_in[3];
    const float* bsig_i  = (const float*)d_in[4];
    const float* log_dec = (const float*)d_in[5];
    const float* theta   = (const float*)d_in[6];
    const float* Bin_r   = (const float*)d_in[7];
    const float* Bin_i   = (const float*)d_in[8];
    const float* Wsh_r   = (const float*)d_in[9];
    const float* Wsh_i   = (const float*)d_in[10];
    const float* bsh_r   = (const float*)d_in[11];
    const float* bsh_i   = (const float*)d_in[12];
    const float* Wfus_r  = (const float*)d_in[13];
    const float* Wfus_i  = (const float*)d_in[14];
    const float* bfus_r  = (const float*)d_in[15];
    const float* bfus_i  = (const float*)d_in[16];
    const float* Wgate   = (const float*)d_in[17];
    const float* bgate   = (const float*)d_in[18];
    float* out = (float*)d_out;

    // dynamic smem for the 2-stage tf32 GEMMs (host attr, no allocation)
    cudaFuncSetAttribute(gemm_tf32<cKA, 1>,
                         cudaFuncAttributeMaxDynamicSharedMemorySize, GEMM_SMEM_BYTES);
    cudaFuncSetAttribute(gemm_tf32<768, 0>,
                         cudaFuncAttributeMaxDynamicSharedMemorySize, GEMM_SMEM_BYTES);

    convert_x<<<cBS * cH / 4 / 256, 256>>>(x);
    // which=0 -> g_Btf (gate weights), which=1 -> g_Bsig_tf (sig weights)
    transpose_tf32<<<dim3(cKA / 32, cH / 32), dim3(32, 8)>>>(Wgate, cH, 0, 0);
    transpose_tf32<<<dim3(cH / 32, 256 / 32), dim3(32, 8)>>>(Wsig_r, 256, 1, 0);
    transpose_tf32<<<dim3(cH / 32, 256 / 32), dim3(32, 8)>>>(Wsig_i, 256, 1, 256);

    // sig: g_sr|g_si = x @ [Wsig_r|Wsig_i] + b   (tf32, N=512, K=768)
    gemm_tf32<768, 0><<<dim3(4, 64), 256, GEMM_SMEM_BYTES>>>(bsig_r, bsig_i, nullptr);

    scan_pass1<<<cBER * cNC, 256>>>(log_dec, theta, Bin_r, Bin_i);
    scan_pass2<<<cBER, 256>>>(log_dec, theta);
    scan_pass3<<<cBER * cNC, 256>>>(log_dec, theta, Bin_r, Bin_i);

    mc_part<<<dim3(28, 8), 256>>>(Wsh_r, Wsh_i, Wfus_r, Wfus_i);
    mc_reduce<<<28 * cH / 256, 256>>>();
    bc_kernel<<<3, 256>>>(bsh_r, bsh_i, Wfus_r, Wfus_i, bfus_r, bfus_i);
    fuse_kernel<<<cBS / 8, 256>>>();

    // gate: out = x + sigmoid([x|fur|fui|z] @ Wgate + bgate) * fur  (tf32)
    gemm_tf32<cKA, 1><<<dim3(6, 64), 256, GEMM_SMEM_BYTES>>>(x, bgate, out);
}